// round 10
// baseline (speedup 1.0000x reference)
#include <cuda_runtime.h>
#include <cuda_bf16.h>
#include <cstdint>

// Shapes (fixed)
#define T_DIM   1024
#define N_BATCH 8
#define E_DIM   1024
#define H_HEADS 16
#define D_HEAD  64
#define B_HEADS 128
#define M_ROWS  8192
#define QKV_LD  3072
#define ROW_STRIDE 24576   // 8*3072

typedef __nv_bfloat16 bf16;

// ---------------- scratch (allocation-free) ----------------
__device__ bf16  g_qh [(size_t)M_ROWS * E_DIM];
__device__ bf16  g_ql [(size_t)M_ROWS * E_DIM];
__device__ bf16  g_wih[(size_t)QKV_LD * E_DIM];
__device__ bf16  g_wil[(size_t)QKV_LD * E_DIM];
__device__ bf16  g_woh[(size_t)E_DIM * E_DIM];
__device__ bf16  g_wol[(size_t)E_DIM * E_DIM];
__device__ bf16  g_qkvh[(size_t)M_ROWS * QKV_LD];
__device__ bf16  g_qkvl[(size_t)M_ROWS * QKV_LD];
__device__ bf16  g_vth[(size_t)N_BATCH * E_DIM * T_DIM];   // [n][d][s]
__device__ bf16  g_vtl[(size_t)N_BATCH * E_DIM * T_DIM];
__device__ float g_attn[(size_t)B_HEADS * T_DIM * T_DIM];
__device__ bf16  g_ph  [(size_t)B_HEADS * T_DIM * T_DIM];
__device__ bf16  g_pl  [(size_t)B_HEADS * T_DIM * T_DIM];
__device__ bf16  g_ch [(size_t)M_ROWS * E_DIM];
__device__ bf16  g_cl [(size_t)M_ROWS * E_DIM];

#define DEVFN __device__ __forceinline__

DEVFN uint32_t smem_u32(const void* p) {
    uint32_t a;
    asm("{ .reg .u64 t; cvta.to.shared.u64 t, %1; cvt.u32.u64 %0, t; }" : "=r"(a) : "l"(p));
    return a;
}
DEVFN void cpa16(uint32_t s, const void* g) {
    asm volatile("cp.async.cg.shared.global [%0], [%1], 16;" :: "r"(s), "l"(g));
}
DEVFN void cp_commit() { asm volatile("cp.async.commit_group;" ::: "memory"); }
template<int N> DEVFN void cp_wait() { asm volatile("cp.async.wait_group %0;" :: "n"(N) : "memory"); }
DEVFN void ldsm4(uint32_t* r, uint32_t a) {
    asm volatile("ldmatrix.sync.aligned.m8n8.x4.shared.b16 {%0,%1,%2,%3}, [%4];"
                 : "=r"(r[0]), "=r"(r[1]), "=r"(r[2]), "=r"(r[3]) : "r"(a));
}
DEVFN void mma16816(float* c, const uint32_t* a, const uint32_t* b) {
    asm volatile(
        "mma.sync.aligned.m16n8k16.row.col.f32.bf16.bf16.f32 "
        "{%0,%1,%2,%3}, {%4,%5,%6,%7}, {%8,%9}, {%0,%1,%2,%3};"
        : "+f"(c[0]), "+f"(c[1]), "+f"(c[2]), "+f"(c[3])
        : "r"(a[0]), "r"(a[1]), "r"(a[2]), "r"(a[3]), "r"(b[0]), "r"(b[1]));
}
DEVFN void split_store2(bf16* ph, bf16* pl, float a, float b) {
    bf16 h0 = __float2bfloat16(a), h1 = __float2bfloat16(b);
    bf16 l0 = __float2bfloat16(a - __bfloat162float(h0));
    bf16 l1 = __float2bfloat16(b - __bfloat162float(h1));
    *reinterpret_cast<__nv_bfloat162*>(ph) = __halves2bfloat162(h0, h1);
    *reinterpret_cast<__nv_bfloat162*>(pl) = __halves2bfloat162(l0, l1);
}

// ---------------------------------------------------------------------------
// Split-bf16 NT GEMM core (ldmatrix + mma.sync): C = alpha*A·B^T (+bias)
// CTA tile 128 x BN, BK=32, 8 warps of WM x WN. Pitch 80B (conflict-free ldsm).
// MMA issue order: three sweeps (HH all accs, HL all accs, LH all accs) to
// maximize same-accumulator reuse distance (16 instead of 1).
// ---------------------------------------------------------------------------
template<int BN, int WM, int WN, bool HAS_BIAS, bool SPLIT_OUT>
DEVFN void gemm_core(const bf16* __restrict__ Ah, const bf16* __restrict__ Al, int lda,
                     const bf16* __restrict__ Bh, const bf16* __restrict__ Bl, int ldb,
                     const float* __restrict__ bias, float alpha,
                     float* __restrict__ C, bf16* __restrict__ Coh, bf16* __restrict__ Col,
                     int ldc, int K, int m0, int n0, char* smem)
{
    constexpr int PITCH = 80;
    constexpr int ASZ = 128 * PITCH;
    constexpr int BSZ = BN  * PITCH;
    constexpr int STAGE = 2 * ASZ + 2 * BSZ;
    const int tid = threadIdx.x;
    const uint32_t sbase = smem_u32(smem);

    auto load_stage = [&](int st, int kk) {
        uint32_t s0 = sbase + st * STAGE;
#pragma unroll
        for (int i = 0; i < 2; ++i) {
            int id = tid + i * 256;
            int row = id >> 2, ck = id & 3;
            uint32_t so = s0 + row * PITCH + ck * 16;
            size_t go = (size_t)(m0 + row) * lda + kk + ck * 8;
            cpa16(so, Ah + go);
            cpa16(so + ASZ, Al + go);
        }
#pragma unroll
        for (int i = 0; i < (BN * 4) / 256; ++i) {
            int id = tid + i * 256;
            int row = id >> 2, ck = id & 3;
            uint32_t so = s0 + 2 * ASZ + row * PITCH + ck * 16;
            size_t go = (size_t)(n0 + row) * ldb + kk + ck * 8;
            cpa16(so, Bh + go);
            cpa16(so + BSZ, Bl + go);
        }
    };

    constexpr int WGM = 128 / WM;
    constexpr int MT = WM / 16, NT = WN / 8;
    const int lane = tid & 31, wid = tid >> 5;
    const int wm = wid % WGM, wn = wid / WGM;
    const int lg = lane >> 3, lr = lane & 7;
    const int r0 = lane >> 2, c0 = (lane & 3) * 2;
    const uint32_t aLOff = (uint32_t)((wm * WM + (lg & 1) * 8 + lr) * PITCH + (lg >> 1) * 16);
    const uint32_t bLOff = (uint32_t)((wn * WN + (lg >> 1) * 8 + lr) * PITCH + (lg & 1) * 16);

    float acc[MT][NT][4];
#pragma unroll
    for (int i = 0; i < MT; i++)
#pragma unroll
        for (int j = 0; j < NT; j++) {
            acc[i][j][0] = 0.f; acc[i][j][1] = 0.f; acc[i][j][2] = 0.f; acc[i][j][3] = 0.f;
        }

    const int NC = K >> 5;
    load_stage(0, 0);
    cp_commit();

    for (int c = 0; c < NC; ++c) {
        if (c + 1 < NC) { load_stage((c + 1) & 1, (c + 1) * 32); cp_commit(); cp_wait<1>(); }
        else            { cp_wait<0>(); }
        __syncthreads();

        const uint32_t sA = sbase + (c & 1) * STAGE;
        const uint32_t sB = sA + 2 * ASZ;
#pragma unroll
        for (int ks = 0; ks < 2; ++ks) {
            uint32_t ah[MT][4], al[MT][4], bh[NT / 2][4], bl[NT / 2][4];
#pragma unroll
            for (int mt = 0; mt < MT; ++mt) {
                ldsm4(ah[mt], sA + aLOff + mt * 16 * PITCH + ks * 32);
                ldsm4(al[mt], sA + ASZ + aLOff + mt * 16 * PITCH + ks * 32);
            }
#pragma unroll
            for (int np = 0; np < NT / 2; ++np) {
                ldsm4(bh[np], sB + bLOff + np * 16 * PITCH + ks * 32);
                ldsm4(bl[np], sB + BSZ + bLOff + np * 16 * PITCH + ks * 32);
            }
            // sweep 1: A_hi x B_hi over all accumulators
#pragma unroll
            for (int mt = 0; mt < MT; ++mt)
#pragma unroll
                for (int nt = 0; nt < NT; ++nt)
                    mma16816(acc[mt][nt], ah[mt], &bh[nt >> 1][(nt & 1) * 2]);
            // sweep 2: A_hi x B_lo
#pragma unroll
            for (int mt = 0; mt < MT; ++mt)
#pragma unroll
                for (int nt = 0; nt < NT; ++nt)
                    mma16816(acc[mt][nt], ah[mt], &bl[nt >> 1][(nt & 1) * 2]);
            // sweep 3: A_lo x B_hi
#pragma unroll
            for (int mt = 0; mt < MT; ++mt)
#pragma unroll
                for (int nt = 0; nt < NT; ++nt)
                    mma16816(acc[mt][nt], al[mt], &bh[nt >> 1][(nt & 1) * 2]);
        }
        __syncthreads();
    }

#pragma unroll
    for (int mt = 0; mt < MT; ++mt) {
#pragma unroll
        for (int nt = 0; nt < NT; ++nt) {
            int row = m0 + wm * WM + mt * 16 + r0;
            int col = n0 + wn * WN + nt * 8 + c0;
            float bx = HAS_BIAS ? bias[col] : 0.f;
            float by = HAS_BIAS ? bias[col + 1] : 0.f;
            float v00 = alpha * acc[mt][nt][0] + bx, v01 = alpha * acc[mt][nt][1] + by;
            float v10 = alpha * acc[mt][nt][2] + bx, v11 = alpha * acc[mt][nt][3] + by;
            if constexpr (SPLIT_OUT) {
                split_store2(Coh + (size_t)row * ldc + col, Col + (size_t)row * ldc + col, v00, v01);
                split_store2(Coh + (size_t)(row + 8) * ldc + col, Col + (size_t)(row + 8) * ldc + col, v10, v11);
            } else {
                *reinterpret_cast<float2*>(C + (size_t)row * ldc + col) = make_float2(v00, v01);
                *reinterpret_cast<float2*>(C + (size_t)(row + 8) * ldc + col) = make_float2(v10, v11);
            }
        }
    }
}

#define SMEM_128 (2 * (2 * 128 * 80 + 2 * 128 * 80))   // 81920
#define SMEM_64  (2 * (2 * 128 * 80 + 2 * 64 * 80))    // 61440

// 1) QKV projection -> (hi, lo) bf16 directly
__global__ __launch_bounds__(256) void k_qkv(const float* __restrict__ bias) {
    extern __shared__ char smem[];
    gemm_core<128, 64, 32, true, true>(g_qh, g_ql, E_DIM, g_wih, g_wil, E_DIM,
                                       bias, 1.f, nullptr, g_qkvh, g_qkvl, QKV_LD, E_DIM,
                                       blockIdx.y * 128, blockIdx.x * 128, smem);
}

// 2) scores = 0.125 * Q K^T -> fp32
__global__ __launch_bounds__(256) void k_scores() {
    extern __shared__ char smem[];
    const int hb = blockIdx.z, n = hb >> 4, h = hb & 15;
    const bf16* Ah = g_qkvh + n * QKV_LD + h * D_HEAD;
    const bf16* Al = g_qkvl + n * QKV_LD + h * D_HEAD;
    float* C = g_attn + ((size_t)hb << 20);
    gemm_core<128, 64, 32, false, false>(Ah, Al, ROW_STRIDE, Ah + E_DIM, Al + E_DIM, ROW_STRIDE,
                                         nullptr, 0.125f, C, nullptr, nullptr, T_DIM, D_HEAD,
                                         blockIdx.y * 128, blockIdx.x * 128, smem);
}

// 3) PV -> ctx (hi, lo) bf16 directly
__global__ __launch_bounds__(256) void k_pv() {
    extern __shared__ char smem[];
    const int hb = blockIdx.y, n = hb >> 4, h = hb & 15;
    const bf16* Ah = g_ph + ((size_t)hb << 20);
    const bf16* Al = g_pl + ((size_t)hb << 20);
    const bf16* Bh = g_vth + ((size_t)n * E_DIM + h * D_HEAD) * T_DIM;
    const bf16* Bl = g_vtl + ((size_t)n * E_DIM + h * D_HEAD) * T_DIM;
    bf16* Ch = g_ch + (size_t)n * E_DIM + h * D_HEAD;
    bf16* Cl = g_cl + (size_t)n * E_DIM + h * D_HEAD;
    gemm_core<64, 32, 32, false, true>(Ah, Al, T_DIM, Bh, Bl, T_DIM,
                                       nullptr, 1.f, nullptr, Ch, Cl, N_BATCH * E_DIM, T_DIM,
                                       blockIdx.x * 128, 0, smem);
}

// 4) out projection -> fp32 final output
__global__ __launch_bounds__(256) void k_out(const float* __restrict__ bias, float* __restrict__ out) {
    extern __shared__ char smem[];
    gemm_core<128, 64, 32, true, false>(g_ch, g_cl, E_DIM, g_woh, g_wol, E_DIM,
                                        bias, 1.f, out, nullptr, nullptr, E_DIM, E_DIM,
                                        blockIdx.y * 128, blockIdx.x * 128, smem);
}

// ---------------------------------------------------------------------------
// Fused softmax + head-average. CTA = (n, t): all 16 heads of one (n,t) row.
// ---------------------------------------------------------------------------
__global__ __launch_bounds__(256) void softmax_avg_kernel(float* __restrict__ outAvg) {
    __shared__ float s_part[8][1024];
    const int bid = blockIdx.x;                 // n*1024 + t
    const int n = bid >> 10, t = bid & 1023;
    const int tid = threadIdx.x, lane = tid & 31, w = tid >> 5;

#pragma unroll
    for (int hh = 0; hh < 2; ++hh) {
        const int h = w + hh * 8;
        const size_t base = ((size_t)(n * 16 + h) << 20) + ((size_t)t << 10);
        const float* row = g_attn + base;

        float4 v[8];
        float mx = -1e30f;
#pragma unroll
        for (int it = 0; it < 8; ++it) {
            v[it] = *reinterpret_cast<const float4*>(row + it * 128 + lane * 4);
            mx = fmaxf(mx, fmaxf(fmaxf(v[it].x, v[it].y), fmaxf(v[it].z, v[it].w)));
        }
#pragma unroll
        for (int o = 16; o; o >>= 1) mx = fmaxf(mx, __shfl_xor_sync(0xffffffffu, mx, o));

        float s = 0.f;
#pragma unroll
        for (int it = 0; it < 8; ++it) {
            v[it].x = __expf(v[it].x - mx);
            v[it].y = __expf(v[it].y - mx);
            v[it].z = __expf(v[it].z - mx);
            v[it].w = __expf(v[it].w - mx);
            s += (v[it].x + v[it].y) + (v[it].z + v[it].w);
        }
#pragma unroll
        for (int o = 16; o; o >>= 1) s += __shfl_xor_sync(0xffffffffu, s, o);
        const float inv = 1.0f / s;

        bf16* ph = g_ph + base;
        bf16* pl = g_pl + base;
#pragma unroll
        for (int it = 0; it < 8; ++it) {
            const int col = it * 128 + lane * 4;
            float p0 = v[it].x * inv, p1 = v[it].y * inv;
            float p2 = v[it].z * inv, p3 = v[it].w * inv;
            bf16 h0 = __float2bfloat16(p0), h1 = __float2bfloat16(p1);
            bf16 h2 = __float2bfloat16(p2), h3 = __float2bfloat16(p3);
            bf16 l0 = __float2bfloat16(p0 - __bfloat162float(h0));
            bf16 l1 = __float2bfloat16(p1 - __bfloat162float(h1));
            bf16 l2 = __float2bfloat16(p2 - __bfloat162float(h2));
            bf16 l3 = __float2bfloat16(p3 - __bfloat162float(h3));
            union { __nv_bfloat162 b[2]; uint2 u; } H, L;
            H.b[0] = __halves2bfloat162(h0, h1); H.b[1] = __halves2bfloat162(h2, h3);
            L.b[0] = __halves2bfloat162(l0, l1); L.b[1] = __halves2bfloat162(l2, l3);
            *reinterpret_cast<uint2*>(ph + col) = H.u;
            *reinterpret_cast<uint2*>(pl + col) = L.u;
            if (hh == 0) {
                s_part[w][col + 0] = p0; s_part[w][col + 1] = p1;
                s_part[w][col + 2] = p2; s_part[w][col + 3] = p3;
            } else {
                s_part[w][col + 0] += p0; s_part[w][col + 1] += p1;
                s_part[w][col + 2] += p2; s_part[w][col + 3] += p3;
            }
        }
    }
    __syncthreads();

    const int col = tid * 4;
    float4 a = *reinterpret_cast<const float4*>(&s_part[0][col]);
#pragma unroll
    for (int p = 1; p < 8; ++p) {
        float4 b = *reinterpret_cast<const float4*>(&s_part[p][col]);
        a.x += b.x; a.y += b.y; a.z += b.z; a.w += b.w;
    }
    const float sc = 1.f / 16.f;
    *reinterpret_cast<float4*>(outAvg + ((size_t)bid << 10) + col) =
        make_float4(a.x * sc, a.y * sc, a.z * sc, a.w * sc);
}

// ---------------- split fp32 -> (hi, lo) bf16 (inputs only) ----------------
__global__ __launch_bounds__(256) void split_kernel(
    const float* __restrict__ x, bf16* __restrict__ h, bf16* __restrict__ l) {
    size_t i = (size_t)blockIdx.x * 256 + threadIdx.x;
    float4 v = reinterpret_cast<const float4*>(x)[i];
    bf16 h0 = __float2bfloat16(v.x), h1 = __float2bfloat16(v.y);
    bf16 h2 = __float2bfloat16(v.z), h3 = __float2bfloat16(v.w);
    bf16 l0 = __float2bfloat16(v.x - __bfloat162float(h0));
    bf16 l1 = __float2bfloat16(v.y - __bfloat162float(h1));
    bf16 l2 = __float2bfloat16(v.z - __bfloat162float(h2));
    bf16 l3 = __float2bfloat16(v.w - __bfloat162float(h3));
    union { __nv_bfloat162 b[2]; uint2 u; } H, L;
    H.b[0] = __halves2bfloat162(h0, h1); H.b[1] = __halves2bfloat162(h2, h3);
    L.b[0] = __halves2bfloat162(l0, l1); L.b[1] = __halves2bfloat162(l2, l3);
    *reinterpret_cast<uint2*>(h + i * 4) = H.u;
    *reinterpret_cast<uint2*>(l + i * 4) = L.u;
}

// ---------------- V transpose (pure bf16 copy of hi and lo planes) ----------------
__global__ __launch_bounds__(256) void vt_kernel() {
    __shared__ bf16 th[32][34];
    __shared__ bf16 tl[32][34];
    const int d0 = blockIdx.x * 32, s0 = blockIdx.y * 32, n = blockIdx.z;
    const int tx = threadIdx.x, ty = threadIdx.y;   // block (32, 8)
#pragma unroll
    for (int j = 0; j < 32; j += 8) {
        const size_t gi = ((size_t)(s0 + ty + j) * N_BATCH + n) * QKV_LD + 2 * E_DIM + d0 + tx;
        th[ty + j][tx] = g_qkvh[gi];
        tl[ty + j][tx] = g_qkvl[gi];
    }
    __syncthreads();
#pragma unroll
    for (int j = 0; j < 32; j += 8) {
        const int d = d0 + ty + j;
        const size_t o = ((size_t)n * E_DIM + d) * T_DIM + s0 + tx;
        g_vth[o] = th[tx][ty + j];
        g_vtl[o] = tl[tx][ty + j];
    }
}

// ---------------- host ----------------
extern "C" void kernel_launch(void* const* d_in, const int* in_sizes, int n_in,
                              void* d_out, int out_size) {
    (void)in_sizes; (void)n_in; (void)out_size;
    const float* query = (const float*)d_in[0];
    const float* in_w  = (const float*)d_in[3];
    const float* in_b  = (const float*)d_in[4];
    const float* out_w = (const float*)d_in[5];
    const float* out_b = (const float*)d_in[6];
    float* out = (float*)d_out;
    float* avg = out + (size_t)M_ROWS * E_DIM;

    void *qh, *ql, *wih, *wil, *woh, *wol;
    cudaGetSymbolAddress(&qh,  g_qh);  cudaGetSymbolAddress(&ql,  g_ql);
    cudaGetSymbolAddress(&wih, g_wih); cudaGetSymbolAddress(&wil, g_wil);
    cudaGetSymbolAddress(&woh, g_woh); cudaGetSymbolAddress(&wol, g_wol);

    cudaFuncSetAttribute(k_qkv,    cudaFuncAttributeMaxDynamicSharedMemorySize, SMEM_128);
    cudaFuncSetAttribute(k_scores, cudaFuncAttributeMaxDynamicSharedMemorySize, SMEM_128);
    cudaFuncSetAttribute(k_pv,     cudaFuncAttributeMaxDynamicSharedMemorySize, SMEM_64);
    cudaFuncSetAttribute(k_out,    cudaFuncAttributeMaxDynamicSharedMemorySize, SMEM_128);

    // input splits
    split_kernel<<<(M_ROWS * E_DIM / 4) / 256, 256>>>(query, (bf16*)qh, (bf16*)ql);
    split_kernel<<<(QKV_LD * E_DIM / 4) / 256, 256>>>(in_w, (bf16*)wih, (bf16*)wil);
    split_kernel<<<(E_DIM * E_DIM / 4) / 256, 256>>>(out_w, (bf16*)woh, (bf16*)wol);

    // 1) QKV projection -> (qkvh, qkvl) directly
    k_qkv<<<dim3(QKV_LD / 128, M_ROWS / 128), 256, SMEM_128>>>(in_b);

    // 2) V transpose (bf16 planes)
    vt_kernel<<<dim3(E_DIM / 32, T_DIM / 32, N_BATCH), dim3(32, 8)>>>();

    // 3) scores = 0.125 * Q K^T -> fp32
    k_scores<<<dim3(T_DIM / 128, T_DIM / 128, B_HEADS), 256, SMEM_128>>>();

    // 4) fused softmax + head-average
    softmax_avg_kernel<<<N_BATCH * T_DIM, 256>>>(avg);

    // 5) PV -> (ch, cl) directly
    k_pv<<<dim3(T_DIM / 128, B_HEADS), 256, SMEM_64>>>();

    // 6) out projection -> first output
    k_out<<<dim3(E_DIM / 128, M_ROWS / 128), 256, SMEM_128>>>(out_b, out);
}

// round 12
// speedup vs baseline: 1.0302x; 1.0302x over previous
#include <cuda_runtime.h>
#include <cuda_bf16.h>
#include <cstdint>

// Shapes (fixed)
#define T_DIM   1024
#define N_BATCH 8
#define E_DIM   1024
#define H_HEADS 16
#define D_HEAD  64
#define B_HEADS 128
#define M_ROWS  8192
#define QKV_LD  3072
#define ROW_STRIDE 24576   // 8*3072

typedef __nv_bfloat16 bf16;

// ---------------- scratch (allocation-free) ----------------
__device__ bf16  g_qh [(size_t)M_ROWS * E_DIM];
__device__ bf16  g_ql [(size_t)M_ROWS * E_DIM];
__device__ bf16  g_wih[(size_t)QKV_LD * E_DIM];
__device__ bf16  g_wil[(size_t)QKV_LD * E_DIM];
__device__ bf16  g_woh[(size_t)E_DIM * E_DIM];
__device__ bf16  g_wol[(size_t)E_DIM * E_DIM];
__device__ bf16  g_qkvh[(size_t)M_ROWS * QKV_LD];
__device__ bf16  g_qkvl[(size_t)M_ROWS * QKV_LD];
__device__ bf16  g_vth[(size_t)N_BATCH * E_DIM * T_DIM];   // [n][d][s]
__device__ bf16  g_vtl[(size_t)N_BATCH * E_DIM * T_DIM];
__device__ float g_attn[(size_t)B_HEADS * T_DIM * T_DIM];  // e = exp(score)
__device__ float g_linv[(size_t)B_HEADS * T_DIM];          // 1 / sum(e) per row
__device__ bf16  g_ch [(size_t)M_ROWS * E_DIM];
__device__ bf16  g_cl [(size_t)M_ROWS * E_DIM];

#define DEVFN __device__ __forceinline__

DEVFN uint32_t smem_u32(const void* p) {
    uint32_t a;
    asm("{ .reg .u64 t; cvta.to.shared.u64 t, %1; cvt.u32.u64 %0, t; }" : "=r"(a) : "l"(p));
    return a;
}
DEVFN void cpa16(uint32_t s, const void* g) {
    asm volatile("cp.async.cg.shared.global [%0], [%1], 16;" :: "r"(s), "l"(g));
}
DEVFN void cp_commit() { asm volatile("cp.async.commit_group;" ::: "memory"); }
template<int N> DEVFN void cp_wait() { asm volatile("cp.async.wait_group %0;" :: "n"(N) : "memory"); }
DEVFN void ldsm4(uint32_t* r, uint32_t a) {
    asm volatile("ldmatrix.sync.aligned.m8n8.x4.shared.b16 {%0,%1,%2,%3}, [%4];"
                 : "=r"(r[0]), "=r"(r[1]), "=r"(r[2]), "=r"(r[3]) : "r"(a));
}
DEVFN void mma16816(float* c, const uint32_t* a, const uint32_t* b) {
    asm volatile(
        "mma.sync.aligned.m16n8k16.row.col.f32.bf16.bf16.f32 "
        "{%0,%1,%2,%3}, {%4,%5,%6,%7}, {%8,%9}, {%0,%1,%2,%3};"
        : "+f"(c[0]), "+f"(c[1]), "+f"(c[2]), "+f"(c[3])
        : "r"(a[0]), "r"(a[1]), "r"(a[2]), "r"(a[3]), "r"(b[0]), "r"(b[1]));
}
DEVFN void split_store2(bf16* ph, bf16* pl, float a, float b) {
    bf16 h0 = __float2bfloat16(a), h1 = __float2bfloat16(b);
    bf16 l0 = __float2bfloat16(a - __bfloat162float(h0));
    bf16 l1 = __float2bfloat16(b - __bfloat162float(h1));
    *reinterpret_cast<__nv_bfloat162*>(ph) = __halves2bfloat162(h0, h1);
    *reinterpret_cast<__nv_bfloat162*>(pl) = __halves2bfloat162(l0, l1);
}

// ---------------------------------------------------------------------------
// Split-bf16 NT GEMM core (ldmatrix + mma.sync): C = f(alpha*A·B^T) (+bias)
// CTA tile 128 x BN, BK=32, 8 warps of WM x WN. Pitch 80B (conflict-free ldsm).
// ---------------------------------------------------------------------------
template<int BN, int WM, int WN, bool HAS_BIAS, bool SPLIT_OUT, bool EXP_OUT>
DEVFN void gemm_core(const bf16* __restrict__ Ah, const bf16* __restrict__ Al, int lda,
                     const bf16* __restrict__ Bh, const bf16* __restrict__ Bl, int ldb,
                     const float* __restrict__ bias, float alpha,
                     float* __restrict__ C, bf16* __restrict__ Coh, bf16* __restrict__ Col,
                     int ldc, int K, int m0, int n0, char* smem)
{
    constexpr int PITCH = 80;
    constexpr int ASZ = 128 * PITCH;
    constexpr int BSZ = BN  * PITCH;
    constexpr int STAGE = 2 * ASZ + 2 * BSZ;
    const int tid = threadIdx.x;
    const uint32_t sbase = smem_u32(smem);

    auto load_stage = [&](int st, int kk) {
        uint32_t s0 = sbase + st * STAGE;
#pragma unroll
        for (int i = 0; i < 2; ++i) {
            int id = tid + i * 256;
            int row = id >> 2, ck = id & 3;
            uint32_t so = s0 + row * PITCH + ck * 16;
            size_t go = (size_t)(m0 + row) * lda + kk + ck * 8;
            cpa16(so, Ah + go);
            cpa16(so + ASZ, Al + go);
        }
#pragma unroll
        for (int i = 0; i < (BN * 4) / 256; ++i) {
            int id = tid + i * 256;
            int row = id >> 2, ck = id & 3;
            uint32_t so = s0 + 2 * ASZ + row * PITCH + ck * 16;
            size_t go = (size_t)(n0 + row) * ldb + kk + ck * 8;
            cpa16(so, Bh + go);
            cpa16(so + BSZ, Bl + go);
        }
    };

    constexpr int WGM = 128 / WM;
    constexpr int MT = WM / 16, NT = WN / 8;
    const int lane = tid & 31, wid = tid >> 5;
    const int wm = wid % WGM, wn = wid / WGM;
    const int lg = lane >> 3, lr = lane & 7;
    const int r0 = lane >> 2, c0 = (lane & 3) * 2;
    const uint32_t aLOff = (uint32_t)((wm * WM + (lg & 1) * 8 + lr) * PITCH + (lg >> 1) * 16);
    const uint32_t bLOff = (uint32_t)((wn * WN + (lg >> 1) * 8 + lr) * PITCH + (lg & 1) * 16);

    float acc[MT][NT][4];
#pragma unroll
    for (int i = 0; i < MT; i++)
#pragma unroll
        for (int j = 0; j < NT; j++) {
            acc[i][j][0] = 0.f; acc[i][j][1] = 0.f; acc[i][j][2] = 0.f; acc[i][j][3] = 0.f;
        }

    const int NC = K >> 5;
    load_stage(0, 0);
    cp_commit();

    for (int c = 0; c < NC; ++c) {
        if (c + 1 < NC) { load_stage((c + 1) & 1, (c + 1) * 32); cp_commit(); cp_wait<1>(); }
        else            { cp_wait<0>(); }
        __syncthreads();

        const uint32_t sA = sbase + (c & 1) * STAGE;
        const uint32_t sB = sA + 2 * ASZ;
#pragma unroll
        for (int ks = 0; ks < 2; ++ks) {
            uint32_t ah[MT][4], al[MT][4], bh[NT / 2][4], bl[NT / 2][4];
#pragma unroll
            for (int mt = 0; mt < MT; ++mt) {
                ldsm4(ah[mt], sA + aLOff + mt * 16 * PITCH + ks * 32);
                ldsm4(al[mt], sA + ASZ + aLOff + mt * 16 * PITCH + ks * 32);
            }
#pragma unroll
            for (int np = 0; np < NT / 2; ++np) {
                ldsm4(bh[np], sB + bLOff + np * 16 * PITCH + ks * 32);
                ldsm4(bl[np], sB + BSZ + bLOff + np * 16 * PITCH + ks * 32);
            }
#pragma unroll
            for (int mt = 0; mt < MT; ++mt)
#pragma unroll
                for (int nt = 0; nt < NT; ++nt)
                    mma16816(acc[mt][nt], ah[mt], &bh[nt >> 1][(nt & 1) * 2]);
#pragma unroll
            for (int mt = 0; mt < MT; ++mt)
#pragma unroll
                for (int nt = 0; nt < NT; ++nt)
                    mma16816(acc[mt][nt], ah[mt], &bl[nt >> 1][(nt & 1) * 2]);
#pragma unroll
            for (int mt = 0; mt < MT; ++mt)
#pragma unroll
                for (int nt = 0; nt < NT; ++nt)
                    mma16816(acc[mt][nt], al[mt], &bh[nt >> 1][(nt & 1) * 2]);
        }
        __syncthreads();
    }

#pragma unroll
    for (int mt = 0; mt < MT; ++mt) {
#pragma unroll
        for (int nt = 0; nt < NT; ++nt) {
            int row = m0 + wm * WM + mt * 16 + r0;
            int col = n0 + wn * WN + nt * 8 + c0;
            float bx = HAS_BIAS ? bias[col] : 0.f;
            float by = HAS_BIAS ? bias[col + 1] : 0.f;
            float v00, v01, v10, v11;
            if constexpr (EXP_OUT) {
                v00 = __expf(alpha * acc[mt][nt][0]); v01 = __expf(alpha * acc[mt][nt][1]);
                v10 = __expf(alpha * acc[mt][nt][2]); v11 = __expf(alpha * acc[mt][nt][3]);
            } else {
                v00 = alpha * acc[mt][nt][0] + bx; v01 = alpha * acc[mt][nt][1] + by;
                v10 = alpha * acc[mt][nt][2] + bx; v11 = alpha * acc[mt][nt][3] + by;
            }
            if constexpr (SPLIT_OUT) {
                split_store2(Coh + (size_t)row * ldc + col, Col + (size_t)row * ldc + col, v00, v01);
                split_store2(Coh + (size_t)(row + 8) * ldc + col, Col + (size_t)(row + 8) * ldc + col, v10, v11);
            } else {
                *reinterpret_cast<float2*>(C + (size_t)row * ldc + col) = make_float2(v00, v01);
                *reinterpret_cast<float2*>(C + (size_t)(row + 8) * ldc + col) = make_float2(v10, v11);
            }
        }
    }
}

#define SMEM_128 (2 * (2 * 128 * 80 + 2 * 128 * 80))   // 81920

// 1) QKV projection -> (hi, lo) bf16 directly
__global__ __launch_bounds__(256) void k_qkv(const float* __restrict__ bias) {
    extern __shared__ char smem[];
    gemm_core<128, 64, 32, true, true, false>(g_qh, g_ql, E_DIM, g_wih, g_wil, E_DIM,
                                              bias, 1.f, nullptr, g_qkvh, g_qkvl, QKV_LD, E_DIM,
                                              blockIdx.y * 128, blockIdx.x * 128, smem);
}

// 2) e = exp(0.125 * Q K^T) -> fp32
__global__ __launch_bounds__(256) void k_scores() {
    extern __shared__ char smem[];
    const int hb = blockIdx.z, n = hb >> 4, h = hb & 15;
    const bf16* Ah = g_qkvh + n * QKV_LD + h * D_HEAD;
    const bf16* Al = g_qkvl + n * QKV_LD + h * D_HEAD;
    float* C = g_attn + ((size_t)hb << 20);
    gemm_core<128, 64, 32, false, false, true>(Ah, Al, ROW_STRIDE, Ah + E_DIM, Al + E_DIM, ROW_STRIDE,
                                               nullptr, 0.125f, C, nullptr, nullptr, T_DIM, D_HEAD,
                                               blockIdx.y * 128, blockIdx.x * 128, smem);
}

// 3) out projection -> fp32 final output
__global__ __launch_bounds__(256) void k_out(const float* __restrict__ bias, float* __restrict__ out) {
    extern __shared__ char smem[];
    gemm_core<128, 64, 32, true, false, false>(g_ch, g_cl, E_DIM, g_woh, g_wol, E_DIM,
                                               bias, 1.f, out, nullptr, nullptr, E_DIM, E_DIM,
                                               blockIdx.y * 128, blockIdx.x * 128, smem);
}

// ---------------------------------------------------------------------------
// lavg: per (n,t) CTA reads e for all 16 heads; computes l=sum(e), writes
// inv_l, and the head-averaged probabilities (second output). No p writes.
// ---------------------------------------------------------------------------
__global__ __launch_bounds__(256) void lavg_kernel(float* __restrict__ outAvg) {
    __shared__ float s_part[8][1024];
    const int bid = blockIdx.x;                 // n*1024 + t
    const int n = bid >> 10, t = bid & 1023;
    const int tid = threadIdx.x, lane = tid & 31, w = tid >> 5;

#pragma unroll
    for (int hh = 0; hh < 2; ++hh) {
        const int h = w + hh * 8;
        const int hb = n * 16 + h;
        const size_t base = ((size_t)hb << 20) + ((size_t)t << 10);
        const float* row = g_attn + base;

        float4 v[8];
        float s = 0.f;
#pragma unroll
        for (int it = 0; it < 8; ++it) {
            v[it] = *reinterpret_cast<const float4*>(row + it * 128 + lane * 4);
            s += (v[it].x + v[it].y) + (v[it].z + v[it].w);
        }
#pragma unroll
        for (int o = 16; o; o >>= 1) s += __shfl_xor_sync(0xffffffffu, s, o);
        const float inv = 1.0f / s;
        if (lane == 0) g_linv[((size_t)hb << 10) + t] = inv;

#pragma unroll
        for (int it = 0; it < 8; ++it) {
            const int col = it * 128 + lane * 4;
            if (hh == 0) {
                s_part[w][col + 0] = v[it].x * inv; s_part[w][col + 1] = v[it].y * inv;
                s_part[w][col + 2] = v[it].z * inv; s_part[w][col + 3] = v[it].w * inv;
            } else {
                s_part[w][col + 0] += v[it].x * inv; s_part[w][col + 1] += v[it].y * inv;
                s_part[w][col + 2] += v[it].z * inv; s_part[w][col + 3] += v[it].w * inv;
            }
        }
    }
    __syncthreads();

    const int col = tid * 4;
    float4 a = *reinterpret_cast<const float4*>(&s_part[0][col]);
#pragma unroll
    for (int p = 1; p < 8; ++p) {
        float4 b = *reinterpret_cast<const float4*>(&s_part[p][col]);
        a.x += b.x; a.y += b.y; a.z += b.z; a.w += b.w;
    }
    const float sc = 1.f / 16.f;
    *reinterpret_cast<float4*>(outAvg + ((size_t)bid << 10) + col) =
        make_float4(a.x * sc, a.y * sc, a.z * sc, a.w * sc);
}

// ---------------------------------------------------------------------------
// PV: O[t][d] = inv_l[t] * sum_s e[t][s] * vt[d][s]. Reads e fp32, converts
// to (hi,lo) bf16 planes in smem, split MMA, epilogue scales by inv_l and
// emits ctx (hi,lo). CTA = (t-tile 128, head). 8 warps: WM=32, WN=32.
// ---------------------------------------------------------------------------
#define PV_RAW_PITCH 144
#define PV_RAWSZ (128 * PV_RAW_PITCH)        // 18432
#define PV_APLANE (128 * 80)                  // 10240
#define PV_VPLANE (64 * 80)                   // 5120
#define PV_VSTAGE (2 * PV_VPLANE)             // 10240
#define PV_CONVH (2 * PV_RAWSZ)               // 36864
#define PV_CONVL (PV_CONVH + PV_APLANE)       // 47104
#define PV_VOFF  (PV_CONVL + PV_APLANE)       // 57344
#define PV_SMEM  (PV_VOFF + 2 * PV_VSTAGE)    // 77824

__global__ __launch_bounds__(256) void k_pv() {
    extern __shared__ char smem[];
    const int tid = threadIdx.x, lane = tid & 31, wid = tid >> 5;
    const uint32_t sbase = smem_u32(smem);
    const int hb = blockIdx.y, n = hb >> 4, h = hb & 15;
    const int t0 = blockIdx.x * 128;

    const float* E  = g_attn + ((size_t)hb << 20) + (size_t)t0 * 1024;
    const bf16* Vh = g_vth + ((size_t)n * E_DIM + h * D_HEAD) * T_DIM;
    const bf16* Vl = g_vtl + ((size_t)n * E_DIM + h * D_HEAD) * T_DIM;

    auto load_stage = [&](int st, int c) {
        uint32_t r0 = sbase + st * PV_RAWSZ;
#pragma unroll
        for (int i = 0; i < 4; ++i) {               // 1024 chunks of 16B (e tile)
            int id = tid + i * 256;
            int row = id >> 3, ck = id & 7;
            cpa16(r0 + row * PV_RAW_PITCH + ck * 16, E + (size_t)row * 1024 + c * 32 + ck * 4);
        }
        uint32_t v0 = sbase + PV_VOFF + st * PV_VSTAGE;
        {
            int row = tid >> 2, ck = tid & 3;       // 64 rows x 4 chunks per plane
            cpa16(v0 + row * 80 + ck * 16, Vh + (size_t)row * 1024 + c * 32 + ck * 8);
            cpa16(v0 + PV_VPLANE + row * 80 + ck * 16, Vl + (size_t)row * 1024 + c * 32 + ck * 8);
        }
    };

    const int wm = wid & 3, wn = wid >> 2;          // WM=32 (4 groups), WN=32 (2 groups)
    const int lg = lane >> 3, lr = lane & 7;
    const int r0 = lane >> 2, c0 = (lane & 3) * 2;
    const uint32_t aLOff = (uint32_t)((wm * 32 + (lg & 1) * 8 + lr) * 80 + (lg >> 1) * 16);
    const uint32_t bLOff = (uint32_t)((wn * 32 + (lg >> 1) * 8 + lr) * 80 + (lg & 1) * 16);

    float acc[2][4][4];
#pragma unroll
    for (int i = 0; i < 2; i++)
#pragma unroll
        for (int j = 0; j < 4; j++) {
            acc[i][j][0] = 0.f; acc[i][j][1] = 0.f; acc[i][j][2] = 0.f; acc[i][j][3] = 0.f;
        }

    load_stage(0, 0);
    cp_commit();

    const int crow = tid >> 1, ccg = (tid & 1) * 16;
    for (int c = 0; c < 32; ++c) {
        if (c + 1 < 32) { load_stage((c + 1) & 1, c + 1); cp_commit(); cp_wait<1>(); }
        else            { cp_wait<0>(); }
        __syncthreads();

        // convert raw e (fp32) -> (hi,lo) bf16 planes
        {
            const char* rp = smem + (c & 1) * PV_RAWSZ + crow * PV_RAW_PITCH + ccg * 4;
            char* hp = smem + PV_CONVH + crow * 80 + ccg * 2;
            char* lp = smem + PV_CONVL + crow * 80 + ccg * 2;
#pragma unroll
            for (int j = 0; j < 16; j += 4) {
                float4 e4 = *reinterpret_cast<const float4*>(rp + j * 4);
                bf16 h0 = __float2bfloat16(e4.x), h1 = __float2bfloat16(e4.y);
                bf16 h2 = __float2bfloat16(e4.z), h3 = __float2bfloat16(e4.w);
                bf16 l0 = __float2bfloat16(e4.x - __bfloat162float(h0));
                bf16 l1 = __float2bfloat16(e4.y - __bfloat162float(h1));
                bf16 l2 = __float2bfloat16(e4.z - __bfloat162float(h2));
                bf16 l3 = __float2bfloat16(e4.w - __bfloat162float(h3));
                union { __nv_bfloat162 b[2]; uint2 u; } H, L;
                H.b[0] = __halves2bfloat162(h0, h1); H.b[1] = __halves2bfloat162(h2, h3);
                L.b[0] = __halves2bfloat162(l0, l1); L.b[1] = __halves2bfloat162(l2, l3);
                *reinterpret_cast<uint2*>(hp + j * 2) = H.u;
                *reinterpret_cast<uint2*>(lp + j * 2) = L.u;
            }
        }
        __syncthreads();

        const uint32_t sV = sbase + PV_VOFF + (c & 1) * PV_VSTAGE;
#pragma unroll
        for (int ks = 0; ks < 2; ++ks) {
            uint32_t ah[2][4], al[2][4], bh[2][4], bl[2][4];
#pragma unroll
            for (int mt = 0; mt < 2; ++mt) {
                ldsm4(ah[mt], sbase + PV_CONVH + aLOff + mt * 16 * 80 + ks * 32);
                ldsm4(al[mt], sbase + PV_CONVL + aLOff + mt * 16 * 80 + ks * 32);
            }
#pragma unroll
            for (int np = 0; np < 2; ++np) {
                ldsm4(bh[np], sV + bLOff + np * 16 * 80 + ks * 32);
                ldsm4(bl[np], sV + PV_VPLANE + bLOff + np * 16 * 80 + ks * 32);
            }
#pragma unroll
            for (int mt = 0; mt < 2; ++mt)
#pragma unroll
                for (int nt = 0; nt < 4; ++nt) {
                    mma16816(acc[mt][nt], ah[mt], &bh[nt >> 1][(nt & 1) * 2]);
                    mma16816(acc[mt][nt], ah[mt], &bl[nt >> 1][(nt & 1) * 2]);
                    mma16816(acc[mt][nt], al[mt], &bh[nt >> 1][(nt & 1) * 2]);
                }
        }
        __syncthreads();
    }

    // epilogue: scale by inv_l, split-store ctx
    const float* linv = g_linv + ((size_t)hb << 10) + t0;
    bf16* Ch = g_ch + (size_t)n * E_DIM + h * D_HEAD;
    bf16* Cl = g_cl + (size_t)n * E_DIM + h * D_HEAD;
#pragma unroll
    for (int mt = 0; mt < 2; ++mt) {
#pragma unroll
        for (int nt = 0; nt < 4; ++nt) {
            int row = wm * 32 + mt * 16 + r0;
            int col = wn * 32 + nt * 8 + c0;
            float il0 = linv[row], il1 = linv[row + 8];
            size_t o0 = (size_t)(t0 + row) * (N_BATCH * E_DIM) + col;
            size_t o1 = (size_t)(t0 + row + 8) * (N_BATCH * E_DIM) + col;
            split_store2(Ch + o0, Cl + o0, acc[mt][nt][0] * il0, acc[mt][nt][1] * il0);
            split_store2(Ch + o1, Cl + o1, acc[mt][nt][2] * il1, acc[mt][nt][3] * il1);
        }
    }
}

// ---------------- split fp32 -> (hi, lo) bf16 (inputs only) ----------------
__global__ __launch_bounds__(256) void split_kernel(
    const float* __restrict__ x, bf16* __restrict__ h, bf16* __restrict__ l) {
    size_t i = (size_t)blockIdx.x * 256 + threadIdx.x;
    float4 v = reinterpret_cast<const float4*>(x)[i];
    bf16 h0 = __float2bfloat16(v.x), h1 = __float2bfloat16(v.y);
    bf16 h2 = __float2bfloat16(v.z), h3 = __float2bfloat16(v.w);
    bf16 l0 = __float2bfloat16(v.x - __bfloat162float(h0));
    bf16 l1 = __float2bfloat16(v.y - __bfloat162float(h1));
    bf16 l2 = __float2bfloat16(v.z - __bfloat162float(h2));
    bf16 l3 = __float2bfloat16(v.w - __bfloat162float(h3));
    union { __nv_bfloat162 b[2]; uint2 u; } H, L;
    H.b[0] = __halves2bfloat162(h0, h1); H.b[1] = __halves2bfloat162(h2, h3);
    L.b[0] = __halves2bfloat162(l0, l1); L.b[1] = __halves2bfloat162(l2, l3);
    *reinterpret_cast<uint2*>(h + i * 4) = H.u;
    *reinterpret_cast<uint2*>(l + i * 4) = L.u;
}

// ---------------- V transpose (pure bf16 copy of hi and lo planes) ----------------
__global__ __launch_bounds__(256) void vt_kernel() {
    __shared__ bf16 th[32][34];
    __shared__ bf16 tl[32][34];
    const int d0 = blockIdx.x * 32, s0 = blockIdx.y * 32, n = blockIdx.z;
    const int tx = threadIdx.x, ty = threadIdx.y;   // block (32, 8)
#pragma unroll
    for (int j = 0; j < 32; j += 8) {
        const size_t gi = ((size_t)(s0 + ty + j) * N_BATCH + n) * QKV_LD + 2 * E_DIM + d0 + tx;
        th[ty + j][tx] = g_qkvh[gi];
        tl[ty + j][tx] = g_qkvl[gi];
    }
    __syncthreads();
#pragma unroll
    for (int j = 0; j < 32; j += 8) {
        const int d = d0 + ty + j;
        const size_t o = ((size_t)n * E_DIM + d) * T_DIM + s0 + tx;
        g_vth[o] = th[tx][ty + j];
        g_vtl[o] = tl[tx][ty + j];
    }
}

// ---------------- host ----------------
extern "C" void kernel_launch(void* const* d_in, const int* in_sizes, int n_in,
                              void* d_out, int out_size) {
    (void)in_sizes; (void)n_in; (void)out_size;
    const float* query = (const float*)d_in[0];
    const float* in_w  = (const float*)d_in[3];
    const float* in_b  = (const float*)d_in[4];
    const float* out_w = (const float*)d_in[5];
    const float* out_b = (const float*)d_in[6];
    float* out = (float*)d_out;
    float* avg = out + (size_t)M_ROWS * E_DIM;

    void *qh, *ql, *wih, *wil, *woh, *wol;
    cudaGetSymbolAddress(&qh,  g_qh);  cudaGetSymbolAddress(&ql,  g_ql);
    cudaGetSymbolAddress(&wih, g_wih); cudaGetSymbolAddress(&wil, g_wil);
    cudaGetSymbolAddress(&woh, g_woh); cudaGetSymbolAddress(&wol, g_wol);

    cudaFuncSetAttribute(k_qkv,    cudaFuncAttributeMaxDynamicSharedMemorySize, SMEM_128);
    cudaFuncSetAttribute(k_scores, cudaFuncAttributeMaxDynamicSharedMemorySize, SMEM_128);
    cudaFuncSetAttribute(k_pv,     cudaFuncAttributeMaxDynamicSharedMemorySize, PV_SMEM);
    cudaFuncSetAttribute(k_out,    cudaFuncAttributeMaxDynamicSharedMemorySize, SMEM_128);

    // input splits
    split_kernel<<<(M_ROWS * E_DIM / 4) / 256, 256>>>(query, (bf16*)qh, (bf16*)ql);
    split_kernel<<<(QKV_LD * E_DIM / 4) / 256, 256>>>(in_w, (bf16*)wih, (bf16*)wil);
    split_kernel<<<(E_DIM * E_DIM / 4) / 256, 256>>>(out_w, (bf16*)woh, (bf16*)wol);

    // 1) QKV projection -> (qkvh, qkvl) directly
    k_qkv<<<dim3(QKV_LD / 128, M_ROWS / 128), 256, SMEM_128>>>(in_b);

    // 2) V transpose (bf16 planes)
    vt_kernel<<<dim3(E_DIM / 32, T_DIM / 32, N_BATCH), dim3(32, 8)>>>();

    // 3) e = exp(scores) -> fp32
    k_scores<<<dim3(T_DIM / 128, T_DIM / 128, B_HEADS), 256, SMEM_128>>>();

    // 4) l + head-average (second output); writes inv_l
    lavg_kernel<<<N_BATCH * T_DIM, 256>>>(avg);

    // 5) PV (reads e + inv_l) -> (ch, cl)
    k_pv<<<dim3(T_DIM / 128, B_HEADS), 256, PV_SMEM>>>();

    // 6) out projection -> first output
    k_out<<<dim3(E_DIM / 128, M_ROWS / 128), 256, SMEM_128>>>(out_b, out);
}

// round 14
// speedup vs baseline: 1.0781x; 1.0465x over previous
#include <cuda_runtime.h>
#include <cuda_bf16.h>
#include <cstdint>

// Shapes (fixed)
#define T_DIM   1024
#define N_BATCH 8
#define E_DIM   1024
#define H_HEADS 16
#define D_HEAD  64
#define B_HEADS 128
#define M_ROWS  8192
#define QKV_LD  3072
#define ROW_STRIDE 24576   // 8*3072

typedef __nv_bfloat16 bf16;

// ---------------- scratch (allocation-free) ----------------
__device__ bf16  g_qh [(size_t)M_ROWS * E_DIM];
__device__ bf16  g_ql [(size_t)M_ROWS * E_DIM];
__device__ bf16  g_wih[(size_t)QKV_LD * E_DIM];
__device__ bf16  g_wil[(size_t)QKV_LD * E_DIM];
__device__ bf16  g_woh[(size_t)E_DIM * E_DIM];
__device__ bf16  g_wol[(size_t)E_DIM * E_DIM];
__device__ bf16  g_qkvh[(size_t)M_ROWS * QKV_LD];
__device__ bf16  g_qkvl[(size_t)M_ROWS * QKV_LD];
__device__ bf16  g_vth[(size_t)N_BATCH * E_DIM * T_DIM];   // [n][d][s]
__device__ bf16  g_vtl[(size_t)N_BATCH * E_DIM * T_DIM];
__device__ float g_attn[(size_t)B_HEADS * T_DIM * T_DIM];  // e = exp(score)
__device__ float g_linv[(size_t)B_HEADS * T_DIM];          // 1 / sum(e) per row
__device__ bf16  g_ch [(size_t)M_ROWS * E_DIM];
__device__ bf16  g_cl [(size_t)M_ROWS * E_DIM];

#define DEVFN __device__ __forceinline__

DEVFN uint32_t smem_u32(const void* p) {
    uint32_t a;
    asm("{ .reg .u64 t; cvta.to.shared.u64 t, %1; cvt.u32.u64 %0, t; }" : "=r"(a) : "l"(p));
    return a;
}
DEVFN void cpa16(uint32_t s, const void* g) {
    asm volatile("cp.async.cg.shared.global [%0], [%1], 16;" :: "r"(s), "l"(g));
}
DEVFN void cp_commit() { asm volatile("cp.async.commit_group;" ::: "memory"); }
template<int N> DEVFN void cp_wait() { asm volatile("cp.async.wait_group %0;" :: "n"(N) : "memory"); }
DEVFN void ldsm4(uint32_t* r, uint32_t a) {
    asm volatile("ldmatrix.sync.aligned.m8n8.x4.shared.b16 {%0,%1,%2,%3}, [%4];"
                 : "=r"(r[0]), "=r"(r[1]), "=r"(r[2]), "=r"(r[3]) : "r"(a));
}
DEVFN void mma16816(float* c, const uint32_t* a, const uint32_t* b) {
    asm volatile(
        "mma.sync.aligned.m16n8k16.row.col.f32.bf16.bf16.f32 "
        "{%0,%1,%2,%3}, {%4,%5,%6,%7}, {%8,%9}, {%0,%1,%2,%3};"
        : "+f"(c[0]), "+f"(c[1]), "+f"(c[2]), "+f"(c[3])
        : "r"(a[0]), "r"(a[1]), "r"(a[2]), "r"(a[3]), "r"(b[0]), "r"(b[1]));
}
DEVFN void split_store2(bf16* ph, bf16* pl, float a, float b) {
    bf16 h0 = __float2bfloat16(a), h1 = __float2bfloat16(b);
    bf16 l0 = __float2bfloat16(a - __bfloat162float(h0));
    bf16 l1 = __float2bfloat16(b - __bfloat162float(h1));
    *reinterpret_cast<__nv_bfloat162*>(ph) = __halves2bfloat162(h0, h1);
    *reinterpret_cast<__nv_bfloat162*>(pl) = __halves2bfloat162(l0, l1);
}

// ---------------------------------------------------------------------------
// Split-bf16 NT GEMM core, 128 threads / 4 warps of 64x64 each.
// CTA tile 128x128, BK=32, pitch-80 smem (conflict-free ldsm), double-buffered.
// 33% less smem read traffic per FLOP than the 8-warp 64x32 variant.
// ---------------------------------------------------------------------------
template<bool HAS_BIAS, bool SPLIT_OUT, bool EXP_OUT>
DEVFN void gemm_core4(const bf16* __restrict__ Ah, const bf16* __restrict__ Al, int lda,
                      const bf16* __restrict__ Bh, const bf16* __restrict__ Bl, int ldb,
                      const float* __restrict__ bias, float alpha,
                      float* __restrict__ C, bf16* __restrict__ Coh, bf16* __restrict__ Col,
                      int ldc, int K, int m0, int n0, char* smem)
{
    constexpr int PITCH = 80;
    constexpr int ASZ = 128 * PITCH;    // 10240
    constexpr int BSZ = 128 * PITCH;
    constexpr int STAGE = 2 * ASZ + 2 * BSZ;   // 40960
    const int tid = threadIdx.x;        // 0..127
    const uint32_t sbase = smem_u32(smem);

    auto load_stage = [&](int st, int kk) {
        uint32_t s0 = sbase + st * STAGE;
#pragma unroll
        for (int i = 0; i < 4; ++i) {   // 512 chunks per plane / 128 threads
            int id = tid + i * 128;
            int row = id >> 2, ck = id & 3;
            uint32_t so = s0 + row * PITCH + ck * 16;
            size_t go = (size_t)(m0 + row) * lda + kk + ck * 8;
            cpa16(so, Ah + go);
            cpa16(so + ASZ, Al + go);
        }
#pragma unroll
        for (int i = 0; i < 4; ++i) {
            int id = tid + i * 128;
            int row = id >> 2, ck = id & 3;
            uint32_t so = s0 + 2 * ASZ + row * PITCH + ck * 16;
            size_t go = (size_t)(n0 + row) * ldb + kk + ck * 8;
            cpa16(so, Bh + go);
            cpa16(so + BSZ, Bl + go);
        }
    };

    const int lane = tid & 31, wid = tid >> 5;     // 4 warps
    const int wm = wid & 1, wn = wid >> 1;         // 2x2 warp grid, 64x64 each
    const int lg = lane >> 3, lr = lane & 7;
    const int r0 = lane >> 2, c0 = (lane & 3) * 2;
    const uint32_t aLOff = (uint32_t)((wm * 64 + (lg & 1) * 8 + lr) * PITCH + (lg >> 1) * 16);
    const uint32_t bLOff = (uint32_t)((wn * 64 + (lg >> 1) * 8 + lr) * PITCH + (lg & 1) * 16);

    float acc[4][8][4];
#pragma unroll
    for (int i = 0; i < 4; i++)
#pragma unroll
        for (int j = 0; j < 8; j++) {
            acc[i][j][0] = 0.f; acc[i][j][1] = 0.f; acc[i][j][2] = 0.f; acc[i][j][3] = 0.f;
        }

    const int NC = K >> 5;
    load_stage(0, 0);
    cp_commit();

    for (int c = 0; c < NC; ++c) {
        if (c + 1 < NC) { load_stage((c + 1) & 1, (c + 1) * 32); cp_commit(); cp_wait<1>(); }
        else            { cp_wait<0>(); }
        __syncthreads();

        const uint32_t sA = sbase + (c & 1) * STAGE;
        const uint32_t sB = sA + 2 * ASZ;
#pragma unroll
        for (int ks = 0; ks < 2; ++ks) {
            uint32_t ah[4][4], al[4][4], bh[4][4], bl[4][4];
#pragma unroll
            for (int mt = 0; mt < 4; ++mt) {
                ldsm4(ah[mt], sA + aLOff + mt * 16 * PITCH + ks * 32);
                ldsm4(al[mt], sA + ASZ + aLOff + mt * 16 * PITCH + ks * 32);
            }
#pragma unroll
            for (int np = 0; np < 4; ++np) {
                ldsm4(bh[np], sB + bLOff + np * 16 * PITCH + ks * 32);
                ldsm4(bl[np], sB + BSZ + bLOff + np * 16 * PITCH + ks * 32);
            }
#pragma unroll
            for (int mt = 0; mt < 4; ++mt)
#pragma unroll
                for (int nt = 0; nt < 8; ++nt)
                    mma16816(acc[mt][nt], ah[mt], &bh[nt >> 1][(nt & 1) * 2]);
#pragma unroll
            for (int mt = 0; mt < 4; ++mt)
#pragma unroll
                for (int nt = 0; nt < 8; ++nt)
                    mma16816(acc[mt][nt], ah[mt], &bl[nt >> 1][(nt & 1) * 2]);
#pragma unroll
            for (int mt = 0; mt < 4; ++mt)
#pragma unroll
                for (int nt = 0; nt < 8; ++nt)
                    mma16816(acc[mt][nt], al[mt], &bh[nt >> 1][(nt & 1) * 2]);
        }
        __syncthreads();
    }

#pragma unroll
    for (int mt = 0; mt < 4; ++mt) {
#pragma unroll
        for (int nt = 0; nt < 8; ++nt) {
            int row = m0 + wm * 64 + mt * 16 + r0;
            int col = n0 + wn * 64 + nt * 8 + c0;
            float bx = HAS_BIAS ? bias[col] : 0.f;
            float by = HAS_BIAS ? bias[col + 1] : 0.f;
            float v00, v01, v10, v11;
            if constexpr (EXP_OUT) {
                v00 = __expf(alpha * acc[mt][nt][0]); v01 = __expf(alpha * acc[mt][nt][1]);
                v10 = __expf(alpha * acc[mt][nt][2]); v11 = __expf(alpha * acc[mt][nt][3]);
            } else {
                v00 = alpha * acc[mt][nt][0] + bx; v01 = alpha * acc[mt][nt][1] + by;
                v10 = alpha * acc[mt][nt][2] + bx; v11 = alpha * acc[mt][nt][3] + by;
            }
            if constexpr (SPLIT_OUT) {
                split_store2(Coh + (size_t)row * ldc + col, Col + (size_t)row * ldc + col, v00, v01);
                split_store2(Coh + (size_t)(row + 8) * ldc + col, Col + (size_t)(row + 8) * ldc + col, v10, v11);
            } else {
                *reinterpret_cast<float2*>(C + (size_t)row * ldc + col) = make_float2(v00, v01);
                *reinterpret_cast<float2*>(C + (size_t)(row + 8) * ldc + col) = make_float2(v10, v11);
            }
        }
    }
}

#define SMEM_128 (2 * (2 * 128 * 80 + 2 * 128 * 80))   // 81920

// 1) QKV projection -> (hi, lo) bf16 directly
__global__ __launch_bounds__(128, 2) void k_qkv(const float* __restrict__ bias) {
    extern __shared__ char smem[];
    gemm_core4<true, true, false>(g_qh, g_ql, E_DIM, g_wih, g_wil, E_DIM,
                                  bias, 1.f, nullptr, g_qkvh, g_qkvl, QKV_LD, E_DIM,
                                  blockIdx.y * 128, blockIdx.x * 128, smem);
}

// 2) e = exp(0.125 * Q K^T) -> fp32
__global__ __launch_bounds__(128, 2) void k_scores() {
    extern __shared__ char smem[];
    const int hb = blockIdx.z, n = hb >> 4, h = hb & 15;
    const bf16* Ah = g_qkvh + n * QKV_LD + h * D_HEAD;
    const bf16* Al = g_qkvl + n * QKV_LD + h * D_HEAD;
    float* C = g_attn + ((size_t)hb << 20);
    gemm_core4<false, false, true>(Ah, Al, ROW_STRIDE, Ah + E_DIM, Al + E_DIM, ROW_STRIDE,
                                   nullptr, 0.125f, C, nullptr, nullptr, T_DIM, D_HEAD,
                                   blockIdx.y * 128, blockIdx.x * 128, smem);
}

// 3) out projection -> fp32 final output
__global__ __launch_bounds__(128, 2) void k_out(const float* __restrict__ bias, float* __restrict__ out) {
    extern __shared__ char smem[];
    gemm_core4<true, false, false>(g_ch, g_cl, E_DIM, g_woh, g_wol, E_DIM,
                                   bias, 1.f, out, nullptr, nullptr, E_DIM, E_DIM,
                                   blockIdx.y * 128, blockIdx.x * 128, smem);
}

// ---------------------------------------------------------------------------
// lavg: per (n,t) CTA reads e for all 16 heads; computes l=sum(e), writes
// inv_l, and the head-averaged probabilities (second output).
// ---------------------------------------------------------------------------
__global__ __launch_bounds__(256) void lavg_kernel(float* __restrict__ outAvg) {
    __shared__ float s_part[8][1024];
    const int bid = blockIdx.x;                 // n*1024 + t
    const int n = bid >> 10, t = bid & 1023;
    const int tid = threadIdx.x, lane = tid & 31, w = tid >> 5;

#pragma unroll
    for (int hh = 0; hh < 2; ++hh) {
        const int h = w + hh * 8;
        const int hb = n * 16 + h;
        const size_t base = ((size_t)hb << 20) + ((size_t)t << 10);
        const float* row = g_attn + base;

        float4 v[8];
        float s = 0.f;
#pragma unroll
        for (int it = 0; it < 8; ++it) {
            v[it] = *reinterpret_cast<const float4*>(row + it * 128 + lane * 4);
            s += (v[it].x + v[it].y) + (v[it].z + v[it].w);
        }
#pragma unroll
        for (int o = 16; o; o >>= 1) s += __shfl_xor_sync(0xffffffffu, s, o);
        const float inv = 1.0f / s;
        if (lane == 0) g_linv[((size_t)hb << 10) + t] = inv;

#pragma unroll
        for (int it = 0; it < 8; ++it) {
            const int col = it * 128 + lane * 4;
            if (hh == 0) {
                s_part[w][col + 0] = v[it].x * inv; s_part[w][col + 1] = v[it].y * inv;
                s_part[w][col + 2] = v[it].z * inv; s_part[w][col + 3] = v[it].w * inv;
            } else {
                s_part[w][col + 0] += v[it].x * inv; s_part[w][col + 1] += v[it].y * inv;
                s_part[w][col + 2] += v[it].z * inv; s_part[w][col + 3] += v[it].w * inv;
            }
        }
    }
    __syncthreads();

    const int col = tid * 4;
    float4 a = *reinterpret_cast<const float4*>(&s_part[0][col]);
#pragma unroll
    for (int p = 1; p < 8; ++p) {
        float4 b = *reinterpret_cast<const float4*>(&s_part[p][col]);
        a.x += b.x; a.y += b.y; a.z += b.z; a.w += b.w;
    }
    const float sc = 1.f / 16.f;
    *reinterpret_cast<float4*>(outAvg + ((size_t)bid << 10) + col) =
        make_float4(a.x * sc, a.y * sc, a.z * sc, a.w * sc);
}

// ---------------------------------------------------------------------------
// PV: O[t][d] = inv_l[t] * sum_s e[t][s] * vt[d][s]. (unchanged from R11)
// ---------------------------------------------------------------------------
#define PV_RAW_PITCH 144
#define PV_RAWSZ (128 * PV_RAW_PITCH)        // 18432
#define PV_APLANE (128 * 80)                  // 10240
#define PV_VPLANE (64 * 80)                   // 5120
#define PV_VSTAGE (2 * PV_VPLANE)             // 10240
#define PV_CONVH (2 * PV_RAWSZ)               // 36864
#define PV_CONVL (PV_CONVH + PV_APLANE)       // 47104
#define PV_VOFF  (PV_CONVL + PV_APLANE)       // 57344
#define PV_SMEM  (PV_VOFF + 2 * PV_VSTAGE)    // 77824

__global__ __launch_bounds__(256) void k_pv() {
    extern __shared__ char smem[];
    const int tid = threadIdx.x, lane = tid & 31, wid = tid >> 5;
    const uint32_t sbase = smem_u32(smem);
    const int hb = blockIdx.y, n = hb >> 4, h = hb & 15;
    const int t0 = blockIdx.x * 128;

    const float* E  = g_attn + ((size_t)hb << 20) + (size_t)t0 * 1024;
    const bf16* Vh = g_vth + ((size_t)n * E_DIM + h * D_HEAD) * T_DIM;
    const bf16* Vl = g_vtl + ((size_t)n * E_DIM + h * D_HEAD) * T_DIM;

    auto load_stage = [&](int st, int c) {
        uint32_t r0 = sbase + st * PV_RAWSZ;
#pragma unroll
        for (int i = 0; i < 4; ++i) {
            int id = tid + i * 256;
            int row = id >> 3, ck = id & 7;
            cpa16(r0 + row * PV_RAW_PITCH + ck * 16, E + (size_t)row * 1024 + c * 32 + ck * 4);
        }
        uint32_t v0 = sbase + PV_VOFF + st * PV_VSTAGE;
        {
            int row = tid >> 2, ck = tid & 3;
            cpa16(v0 + row * 80 + ck * 16, Vh + (size_t)row * 1024 + c * 32 + ck * 8);
            cpa16(v0 + PV_VPLANE + row * 80 + ck * 16, Vl + (size_t)row * 1024 + c * 32 + ck * 8);
        }
    };

    const int wm = wid & 3, wn = wid >> 2;
    const int lg = lane >> 3, lr = lane & 7;
    const int r0 = lane >> 2, c0 = (lane & 3) * 2;
    const uint32_t aLOff = (uint32_t)((wm * 32 + (lg & 1) * 8 + lr) * 80 + (lg >> 1) * 16);
    const uint32_t bLOff = (uint32_t)((wn * 32 + (lg >> 1) * 8 + lr) * 80 + (lg & 1) * 16);

    float acc[2][4][4];
#pragma unroll
    for (int i = 0; i < 2; i++)
#pragma unroll
        for (int j = 0; j < 4; j++) {
            acc[i][j][0] = 0.f; acc[i][j][1] = 0.f; acc[i][j][2] = 0.f; acc[i][j][3] = 0.f;
        }

    load_stage(0, 0);
    cp_commit();

    const int crow = tid >> 1, ccg = (tid & 1) * 16;
    for (int c = 0; c < 32; ++c) {
        if (c + 1 < 32) { load_stage((c + 1) & 1, c + 1); cp_commit(); cp_wait<1>(); }
        else            { cp_wait<0>(); }
        __syncthreads();

        {
            const char* rp = smem + (c & 1) * PV_RAWSZ + crow * PV_RAW_PITCH + ccg * 4;
            char* hp = smem + PV_CONVH + crow * 80 + ccg * 2;
            char* lp = smem + PV_CONVL + crow * 80 + ccg * 2;
#pragma unroll
            for (int j = 0; j < 16; j += 4) {
                float4 e4 = *reinterpret_cast<const float4*>(rp + j * 4);
                bf16 h0 = __float2bfloat16(e4.x), h1 = __float2bfloat16(e4.y);
                bf16 h2 = __float2bfloat16(e4.z), h3 = __float2bfloat16(e4.w);
                bf16 l0 = __float2bfloat16(e4.x - __bfloat162float(h0));
                bf16 l1 = __float2bfloat16(e4.y - __bfloat162float(h1));
                bf16 l2 = __float2bfloat16(e4.z - __bfloat162float(h2));
                bf16 l3 = __float2bfloat16(e4.w - __bfloat162float(h3));
                union { __nv_bfloat162 b[2]; uint2 u; } H, L;
                H.b[0] = __halves2bfloat162(h0, h1); H.b[1] = __halves2bfloat162(h2, h3);
                L.b[0] = __halves2bfloat162(l0, l1); L.b[1] = __halves2bfloat162(l2, l3);
                *reinterpret_cast<uint2*>(hp + j * 2) = H.u;
                *reinterpret_cast<uint2*>(lp + j * 2) = L.u;
            }
        }
        __syncthreads();

        const uint32_t sV = sbase + PV_VOFF + (c & 1) * PV_VSTAGE;
#pragma unroll
        for (int ks = 0; ks < 2; ++ks) {
            uint32_t ah[2][4], al[2][4], bh[2][4], bl[2][4];
#pragma unroll
            for (int mt = 0; mt < 2; ++mt) {
                ldsm4(ah[mt], sbase + PV_CONVH + aLOff + mt * 16 * 80 + ks * 32);
                ldsm4(al[mt], sbase + PV_CONVL + aLOff + mt * 16 * 80 + ks * 32);
            }
#pragma unroll
            for (int np = 0; np < 2; ++np) {
                ldsm4(bh[np], sV + bLOff + np * 16 * 80 + ks * 32);
                ldsm4(bl[np], sV + PV_VPLANE + bLOff + np * 16 * 80 + ks * 32);
            }
#pragma unroll
            for (int mt = 0; mt < 2; ++mt)
#pragma unroll
                for (int nt = 0; nt < 4; ++nt) {
                    mma16816(acc[mt][nt], ah[mt], &bh[nt >> 1][(nt & 1) * 2]);
                    mma16816(acc[mt][nt], ah[mt], &bl[nt >> 1][(nt & 1) * 2]);
                    mma16816(acc[mt][nt], al[mt], &bh[nt >> 1][(nt & 1) * 2]);
                }
        }
        __syncthreads();
    }

    const float* linv = g_linv + ((size_t)hb << 10) + t0;
    bf16* Ch = g_ch + (size_t)n * E_DIM + h * D_HEAD;
    bf16* Cl = g_cl + (size_t)n * E_DIM + h * D_HEAD;
#pragma unroll
    for (int mt = 0; mt < 2; ++mt) {
#pragma unroll
        for (int nt = 0; nt < 4; ++nt) {
            int row = wm * 32 + mt * 16 + r0;
            int col = wn * 32 + nt * 8 + c0;
            float il0 = linv[row], il1 = linv[row + 8];
            size_t o0 = (size_t)(t0 + row) * (N_BATCH * E_DIM) + col;
            size_t o1 = (size_t)(t0 + row + 8) * (N_BATCH * E_DIM) + col;
            split_store2(Ch + o0, Cl + o0, acc[mt][nt][0] * il0, acc[mt][nt][1] * il0);
            split_store2(Ch + o1, Cl + o1, acc[mt][nt][2] * il1, acc[mt][nt][3] * il1);
        }
    }
}

// ---------------- split fp32 -> (hi, lo) bf16 (inputs only) ----------------
__global__ __launch_bounds__(256) void split_kernel(
    const float* __restrict__ x, bf16* __restrict__ h, bf16* __restrict__ l) {
    size_t i = (size_t)blockIdx.x * 256 + threadIdx.x;
    float4 v = reinterpret_cast<const float4*>(x)[i];
    bf16 h0 = __float2bfloat16(v.x), h1 = __float2bfloat16(v.y);
    bf16 h2 = __float2bfloat16(v.z), h3 = __float2bfloat16(v.w);
    bf16 l0 = __float2bfloat16(v.x - __bfloat162float(h0));
    bf16 l1 = __float2bfloat16(v.y - __bfloat162float(h1));
    bf16 l2 = __float2bfloat16(v.z - __bfloat162float(h2));
    bf16 l3 = __float2bfloat16(v.w - __bfloat162float(h3));
    union { __nv_bfloat162 b[2]; uint2 u; } H, L;
    H.b[0] = __halves2bfloat162(h0, h1); H.b[1] = __halves2bfloat162(h2, h3);
    L.b[0] = __halves2bfloat162(l0, l1); L.b[1] = __halves2bfloat162(l2, l3);
    *reinterpret_cast<uint2*>(h + i * 4) = H.u;
    *reinterpret_cast<uint2*>(l + i * 4) = L.u;
}

// ---------------- V transpose (pure bf16 copy of hi and lo planes) ----------------
__global__ __launch_bounds__(256) void vt_kernel() {
    __shared__ bf16 th[32][34];
    __shared__ bf16 tl[32][34];
    const int d0 = blockIdx.x * 32, s0 = blockIdx.y * 32, n = blockIdx.z;
    const int tx = threadIdx.x, ty = threadIdx.y;   // block (32, 8)
#pragma unroll
    for (int j = 0; j < 32; j += 8) {
        const size_t gi = ((size_t)(s0 + ty + j) * N_BATCH + n) * QKV_LD + 2 * E_DIM + d0 + tx;
        th[ty + j][tx] = g_qkvh[gi];
        tl[ty + j][tx] = g_qkvl[gi];
    }
    __syncthreads();
#pragma unroll
    for (int j = 0; j < 32; j += 8) {
        const int d = d0 + ty + j;
        const size_t o = ((size_t)n * E_DIM + d) * T_DIM + s0 + tx;
        g_vth[o] = th[tx][ty + j];
        g_vtl[o] = tl[tx][ty + j];
    }
}

// ---------------- host ----------------
extern "C" void kernel_launch(void* const* d_in, const int* in_sizes, int n_in,
                              void* d_out, int out_size) {
    (void)in_sizes; (void)n_in; (void)out_size;
    const float* query = (const float*)d_in[0];
    const float* in_w  = (const float*)d_in[3];
    const float* in_b  = (const float*)d_in[4];
    const float* out_w = (const float*)d_in[5];
    const float* out_b = (const float*)d_in[6];
    float* out = (float*)d_out;
    float* avg = out + (size_t)M_ROWS * E_DIM;

    void *qh, *ql, *wih, *wil, *woh, *wol;
    cudaGetSymbolAddress(&qh,  g_qh);  cudaGetSymbolAddress(&ql,  g_ql);
    cudaGetSymbolAddress(&wih, g_wih); cudaGetSymbolAddress(&wil, g_wil);
    cudaGetSymbolAddress(&woh, g_woh); cudaGetSymbolAddress(&wol, g_wol);

    cudaFuncSetAttribute(k_qkv,    cudaFuncAttributeMaxDynamicSharedMemorySize, SMEM_128);
    cudaFuncSetAttribute(k_scores, cudaFuncAttributeMaxDynamicSharedMemorySize, SMEM_128);
    cudaFuncSetAttribute(k_pv,     cudaFuncAttributeMaxDynamicSharedMemorySize, PV_SMEM);
    cudaFuncSetAttribute(k_out,    cudaFuncAttributeMaxDynamicSharedMemorySize, SMEM_128);

    // input splits
    split_kernel<<<(M_ROWS * E_DIM / 4) / 256, 256>>>(query, (bf16*)qh, (bf16*)ql);
    split_kernel<<<(QKV_LD * E_DIM / 4) / 256, 256>>>(in_w, (bf16*)wih, (bf16*)wil);
    split_kernel<<<(E_DIM * E_DIM / 4) / 256, 256>>>(out_w, (bf16*)woh, (bf16*)wol);

    // 1) QKV projection -> (qkvh, qkvl) directly
    k_qkv<<<dim3(QKV_LD / 128, M_ROWS / 128), 128, SMEM_128>>>(in_b);

    // 2) V transpose (bf16 planes)
    vt_kernel<<<dim3(E_DIM / 32, T_DIM / 32, N_BATCH), dim3(32, 8)>>>();

    // 3) e = exp(scores) -> fp32
    k_scores<<<dim3(T_DIM / 128, T_DIM / 128, B_HEADS), 128, SMEM_128>>>();

    // 4) l + head-average (second output); writes inv_l
    lavg_kernel<<<N_BATCH * T_DIM, 256>>>(avg);

    // 5) PV (reads e + inv_l) -> (ch, cl)
    k_pv<<<dim3(T_DIM / 128, B_HEADS), 256, PV_SMEM>>>();

    // 6) out projection -> first output
    k_out<<<dim3(E_DIM / 128, M_ROWS / 128), 128, SMEM_128>>>(out_b, out);
}